// round 15
// baseline (speedup 1.0000x reference)
#include <cuda_runtime.h>
#include <cuda_fp16.h>
#include <math.h>
#include <stdint.h>

#define NN   40000
#define NP   40064          // 313 * 128, padded
#define EE   640000
#define FIN  33
#define HH   128
#define LL   8
#define ALPHA 0.1f
#define DEGCAP 64

// ---------------- scratch (no allocation allowed) ----------------
__device__ float  g_x0[NP * HH];
__device__ float  g_xca[NP * HH];           // fp32 ping
__device__ float  g_xcb[NP * HH];           // fp32 pong
__device__ __half g_xha[NP * HH];           // fp16 scaled xc mirror ping
__device__ __half g_xhb[NP * HH];           // fp16 scaled xc mirror pong
__device__ float  g_xx[NP * HH];            // aggregation output fp32
__device__ __half g_xxh[NP * HH];           // aggregation output fp16 (scaled)
__device__ __half g_wh[LL * HH * HH];       // W^T fp16: [l][n][k]
__device__ int    g_cnt[NN];
__device__ int    g_ecol[(size_t)NN * DEGCAP];
__device__ float  g_ew[(size_t)NN * DEGCAP];

// ---------------- launch 0: zero cnt + Wh = fp16(W^T) ----------------
__global__ void prep_kernel(const float* __restrict__ Wc) {
    int idx = blockIdx.x * blockDim.x + threadIdx.x;
    if (idx < NN) g_cnt[idx] = 0;
    if (idx < LL * HH * HH) {
        int l = idx >> 14;
        int rem = idx & 16383;
        int n = rem >> 7, k = rem & 127;
        g_wh[idx] = __float2half_rn(Wc[(l << 14) + k * HH + n]);
    }
}

// ---------------- launch 1: input projection + ELL scatter (fused) ----------------
#define SCAT_BLOCKS 2500
#define INP_BLOCKS  1250
__global__ void input_scatter_kernel(const float* __restrict__ x,
                                     const float* __restrict__ Win,
                                     const float* __restrict__ bin,
                                     const int* __restrict__ er,
                                     const int* __restrict__ ec,
                                     const float* __restrict__ ew) {
    if (blockIdx.x < SCAT_BLOCKS) {
        int e = blockIdx.x * 256 + threadIdx.x;
        if (e < EE) {
            int r = er[e];
            int s = atomicAdd(&g_cnt[r], 1);
            if (s < DEGCAP) {
                g_ecol[(size_t)r * DEGCAP + s] = ec[e];
                g_ew[(size_t)r * DEGCAP + s] = ew[e];
            }
        }
        return;
    }
    // input projection part: 128 effective threads, all 256 join barriers
    __shared__ float sW[HH * FIN];
    __shared__ float sx[FIN];
    int tid = threadIdx.x;
    for (int i = tid; i < HH * FIN; i += 256) sW[i] = Win[i];
    float b = (tid < HH) ? bin[tid] : 0.f;
    int row0 = (blockIdx.x - SCAT_BLOCKS) * 32;
    for (int r = 0; r < 32; r++) {
        int row = row0 + r;
        __syncthreads();
        if (tid < FIN) sx[tid] = x[row * FIN + tid];
        __syncthreads();
        if (tid < HH) {
            float s = b;
#pragma unroll
            for (int f = 0; f < FIN; f++) s += sW[tid * FIN + f] * sx[f];
            s = fmaxf(s, 0.0f);
            g_x0[row * HH + tid] = s;
            g_xca[row * HH + tid] = s;
            g_xha[row * HH + tid] = __float2half_rn(s);
        }
    }
}

// ---------------- SpMM: g_xx = invs*(A @ srcH) + 0.1*x0 ; g_xxh = g_xx * sxx ----
__device__ __forceinline__ void acc8(float* a, uint4 d, float w) {
    float2 f0 = __half22float2(*(__half2*)&d.x);
    float2 f1 = __half22float2(*(((__half2*)&d.x) + 1));
    float2 f2 = __half22float2(*(__half2*)&d.z);
    float2 f3 = __half22float2(*(((__half2*)&d.z) + 1));
    a[0] += w * f0.x; a[1] += w * f0.y;
    a[2] += w * f1.x; a[3] += w * f1.y;
    a[4] += w * f2.x; a[5] += w * f2.y;
    a[6] += w * f3.x; a[7] += w * f3.y;
}

__global__ void spmm_kernel(const __half* __restrict__ srcH, float invs, float sxx) {
    int gt = blockIdx.x * blockDim.x + threadIdx.x;
    int warp = gt >> 5;
    int lane = threadIdx.x & 31;
    int hsel = lane >> 4;
    int hl = lane & 15;
    int row = warp * 2 + hsel;
    if (row >= NN) return;
    int cn = g_cnt[row];
    cn = cn < DEGCAP ? cn : DEGCAP;
    const int* cb = g_ecol + (size_t)row * DEGCAP;
    const float* wb = g_ew + (size_t)row * DEGCAP;

    float aA[8] = {0.f, 0.f, 0.f, 0.f, 0.f, 0.f, 0.f, 0.f};
    float aB[8] = {0.f, 0.f, 0.f, 0.f, 0.f, 0.f, 0.f, 0.f};
    int fo = hl * 8;
    int i = 0;
    for (; i + 4 <= cn; i += 4) {
        int4 c = *(const int4*)&cb[i];
        float4 w = *(const float4*)&wb[i];
        uint4 d0 = *(const uint4*)&srcH[(size_t)c.x * HH + fo];
        uint4 d1 = *(const uint4*)&srcH[(size_t)c.y * HH + fo];
        uint4 d2 = *(const uint4*)&srcH[(size_t)c.z * HH + fo];
        uint4 d3 = *(const uint4*)&srcH[(size_t)c.w * HH + fo];
        acc8(aA, d0, w.x);
        acc8(aB, d1, w.y);
        acc8(aA, d2, w.z);
        acc8(aB, d3, w.w);
    }
    for (; i < cn; i++) {
        int c = cb[i];
        float w = wb[i];
        uint4 d = *(const uint4*)&srcH[(size_t)c * HH + fo];
        acc8(aA, d, w);
    }
#pragma unroll
    for (int j = 0; j < 8; j++) aA[j] += aB[j];

    const float* x0p = &g_x0[(size_t)row * HH + fo];
    float4 x00 = *(const float4*)x0p;
    float4 x01 = *(const float4*)(x0p + 4);
    float o[8];
    o[0] = invs * aA[0] + ALPHA * x00.x;
    o[1] = invs * aA[1] + ALPHA * x00.y;
    o[2] = invs * aA[2] + ALPHA * x00.z;
    o[3] = invs * aA[3] + ALPHA * x00.w;
    o[4] = invs * aA[4] + ALPHA * x01.x;
    o[5] = invs * aA[5] + ALPHA * x01.y;
    o[6] = invs * aA[6] + ALPHA * x01.z;
    o[7] = invs * aA[7] + ALPHA * x01.w;
    float* xxp = &g_xx[(size_t)row * HH + fo];
    *(float4*)xxp = make_float4(o[0], o[1], o[2], o[3]);
    *(float4*)(xxp + 4) = make_float4(o[4], o[5], o[6], o[7]);
    __half2 h0 = __floats2half2_rn(o[0] * sxx, o[1] * sxx);
    __half2 h1 = __floats2half2_rn(o[2] * sxx, o[3] * sxx);
    __half2 h2 = __floats2half2_rn(o[4] * sxx, o[5] * sxx);
    __half2 h3 = __floats2half2_rn(o[6] * sxx, o[7] * sxx);
    uint4 hp;
    hp.x = *(const unsigned*)&h0;
    hp.y = *(const unsigned*)&h1;
    hp.z = *(const unsigned*)&h2;
    hp.w = *(const unsigned*)&h3;
    *(uint4*)&g_xxh[(size_t)row * HH + fo] = hp;
}

// ---------------- GEMM (HMMA + ldmatrix): out = (1-b)*xx + b*(xx@W); residual ----
// CTA 128x128x128, 8 warps (4m x 2n), warp tile 32x64.
// smem stride 136 halfs (272B rows) => conflict-free LDSM phases.
#define MSTR 136
#define SMEM_MMA (2 * 128 * MSTR * 2)

__device__ __forceinline__ void hmma(float* d, const uint32_t* a,
                                     uint32_t b0, uint32_t b1) {
    asm volatile(
        "mma.sync.aligned.m16n8k16.row.col.f32.f16.f16.f32 "
        "{%0,%1,%2,%3}, {%4,%5,%6,%7}, {%8,%9}, {%0,%1,%2,%3};"
        : "+f"(d[0]), "+f"(d[1]), "+f"(d[2]), "+f"(d[3])
        : "r"(a[0]), "r"(a[1]), "r"(a[2]), "r"(a[3]), "r"(b0), "r"(b1));
}
#define LDSM_X4(r, addr) \
    asm volatile("ldmatrix.sync.aligned.m8n8.x4.shared.b16 {%0,%1,%2,%3}, [%4];" \
        : "=r"((r)[0]), "=r"((r)[1]), "=r"((r)[2]), "=r"((r)[3]) : "r"(addr))

__global__ void __launch_bounds__(256) mma_gemm_kernel(const float* __restrict__ src,
                                                       float* __restrict__ dst,
                                                       __half* __restrict__ dstH,
                                                       const __half* __restrict__ Wh,
                                                       float omb, float bscale,
                                                       float hscale) {
    extern __shared__ __half sh[];
    __half* As = sh;               // [128][MSTR]
    __half* Bs = sh + 128 * MSTR;  // [128][MSTR], [n][k]

    int tid = threadIdx.x;
    int r0 = blockIdx.x * 128;
    const __half* Axh = g_xxh + (size_t)r0 * HH;

    // stage A and B tiles (8 uint4 each per thread)
#pragma unroll
    for (int i = 0; i < 8; i++) {
        int idx = tid + i * 256;            // 0..2047
        int row = idx >> 4, q = idx & 15;
        *(uint4*)&As[row * MSTR + q * 8] = *(const uint4*)&Axh[row * HH + q * 8];
        *(uint4*)&Bs[row * MSTR + q * 8] = *(const uint4*)&Wh[row * HH + q * 8];
    }
    __syncthreads();

    int wid = tid >> 5, lane = tid & 31;
    int wm = wid >> 1, wn = wid & 1;
    int qid = lane >> 2, qt = lane & 3;

    uint32_t As_u = (uint32_t)__cvta_generic_to_shared(As);
    uint32_t Bs_u = (uint32_t)__cvta_generic_to_shared(Bs);

    // ldmatrix base addresses (bytes), k-offset added per k-step
    uint32_t aaddr[2], baddr[4];
#pragma unroll
    for (int mt = 0; mt < 2; mt++)
        aaddr[mt] = As_u + ((wm * 32 + mt * 16 + (lane & 15)) * MSTR
                            + (lane >> 4) * 8) * 2;
#pragma unroll
    for (int j = 0; j < 4; j++)
        baddr[j] = Bs_u + ((wn * 64 + j * 16 + ((lane >> 4) & 1) * 8 + (lane & 7)) * MSTR
                           + ((lane >> 3) & 1) * 8) * 2;

    float acc[2][8][4];
#pragma unroll
    for (int mt = 0; mt < 2; mt++)
#pragma unroll
        for (int nt = 0; nt < 8; nt++)
#pragma unroll
            for (int c = 0; c < 4; c++) acc[mt][nt][c] = 0.f;

#pragma unroll
    for (int ks = 0; ks < 8; ks++) {
        uint32_t ko = ks * 32;              // 16 halfs = 32 bytes
        uint32_t a[2][4];
        LDSM_X4(a[0], aaddr[0] + ko);
        LDSM_X4(a[1], aaddr[1] + ko);
#pragma unroll
        for (int j = 0; j < 4; j++) {
            uint32_t bf[4];
            LDSM_X4(bf, baddr[j] + ko);
            hmma(acc[0][2 * j + 0], a[0], bf[0], bf[1]);
            hmma(acc[1][2 * j + 0], a[1], bf[0], bf[1]);
            hmma(acc[0][2 * j + 1], a[0], bf[2], bf[3]);
            hmma(acc[1][2 * j + 1], a[1], bf[2], bf[3]);
        }
    }

    // epilogue: dst = src + relu(omb*xx + bscale*acc); mirror = dst*hscale
#pragma unroll
    for (int mt = 0; mt < 2; mt++) {
#pragma unroll
        for (int h = 0; h < 2; h++) {
            int row = r0 + wm * 32 + mt * 16 + qid + 8 * h;
            const float* xxr = &g_xx[(size_t)row * HH];
            const float* srr = &src[(size_t)row * HH];
            float* dsr = &dst[(size_t)row * HH];
            __half* dhr = &dstH[(size_t)row * HH];
#pragma unroll
            for (int nt = 0; nt < 8; nt++) {
                int col = wn * 64 + nt * 8 + qt * 2;
                float v0 = acc[mt][nt][2 * h + 0];
                float v1 = acc[mt][nt][2 * h + 1];
                float2 xx = *(const float2*)&xxr[col];
                float o0 = omb * xx.x + bscale * v0;
                float o1 = omb * xx.y + bscale * v1;
                float2 sv = *(const float2*)&srr[col];
                float d0 = sv.x + fmaxf(o0, 0.f);
                float d1 = sv.y + fmaxf(o1, 0.f);
                *(float2*)&dsr[col] = make_float2(d0, d1);
                __half2 hm = __floats2half2_rn(d0 * hscale, d1 * hscale);
                *(unsigned*)&dhr[col] = *(const unsigned*)&hm;
            }
        }
    }
}

// ---------------- output projection: out = xc @ W_out^T + b_out ----------------
__global__ void out_proj_kernel(const float* __restrict__ xc,
                                const float* __restrict__ Wout,
                                const float* __restrict__ bout,
                                float* __restrict__ out) {
    int gt = blockIdx.x * blockDim.x + threadIdx.x;
    int row = gt >> 5;
    int lane = threadIdx.x & 31;
    if (row >= NN) return;
    float4 v = ((const float4*)xc)[row * 32 + lane];
#pragma unroll
    for (int c = 0; c < 3; c++) {
        float4 w = *(const float4*)&Wout[c * HH + lane * 4];
        float s = v.x * w.x + v.y * w.y + v.z * w.z + v.w * w.w;
#pragma unroll
        for (int o = 16; o; o >>= 1) s += __shfl_down_sync(0xFFFFFFFFu, s, o);
        if (lane == 0) out[row * 3 + c] = s + bout[c];
    }
}

extern "C" void kernel_launch(void* const* d_in, const int* in_sizes, int n_in,
                              void* d_out, int out_size) {
    const float* x    = (const float*)d_in[0];
    const int*   er   = (const int*)d_in[1];
    const int*   ec   = (const int*)d_in[2];
    const float* ew   = (const float*)d_in[3];
    const float* Win  = (const float*)d_in[4];
    const float* bin  = (const float*)d_in[5];
    const float* Wout = (const float*)d_in[6];
    const float* bout = (const float*)d_in[7];
    const float* Wc   = (const float*)d_in[8];
    float* out = (float*)d_out;

    float*  bufA; cudaGetSymbolAddress((void**)&bufA, g_xca);
    float*  bufB; cudaGetSymbolAddress((void**)&bufB, g_xcb);
    __half* hbufA; cudaGetSymbolAddress((void**)&hbufA, g_xha);
    __half* hbufB; cudaGetSymbolAddress((void**)&hbufB, g_xhb);
    __half* wh;   cudaGetSymbolAddress((void**)&wh, g_wh);

    cudaFuncSetAttribute(mma_gemm_kernel,
                         cudaFuncAttributeMaxDynamicSharedMemorySize, SMEM_MMA);

    prep_kernel<<<(LL * HH * HH + 255) / 256, 256>>>(Wc);                // launch 0
    input_scatter_kernel<<<SCAT_BLOCKS + INP_BLOCKS, 256>>>(x, Win, bin,
                                                            er, ec, ew); // launch 1

    for (int l = 0; l < LL; l++) {
        const float*  src  = (l & 1) ? bufB : bufA;
        float*        dst  = (l & 1) ? bufA : bufB;
        const __half* srcH = (l & 1) ? hbufB : hbufA;
        __half*       dstH = (l & 1) ? hbufA : hbufB;
        float beta = logf(0.5f / (float)(l + 1) + 1.0f);
        float invs = ldexpf(0.9f, 3 * l);            // 0.9 * 2^{3l}
        float sxx = ldexpf(1.0f, -3 * l);            // 2^{-3l}
        float bscale = beta * ldexpf(1.0f, 3 * l);   // beta * 2^{3l}
        float hscale = ldexpf(1.0f, -3 * (l + 1));   // 2^{-3(l+1)}
        spmm_kernel<<<(NN / 2 * 32 + 255) / 256, 256>>>(srcH, invs, sxx); // launch 2
        mma_gemm_kernel<<<NP / 128, 256, SMEM_MMA>>>(src, dst, dstH,      // launch 3 = profiled
                                                     wh + (size_t)l * HH * HH,
                                                     1.0f - beta, bscale, hscale);
    }

    out_proj_kernel<<<(NN * 32 + 255) / 256, 256>>>(bufA, Wout, bout, out);
}

// round 16
// speedup vs baseline: 1.0430x; 1.0430x over previous
#include <cuda_runtime.h>
#include <cuda_fp16.h>
#include <math.h>
#include <stdint.h>

#define NN   40000
#define NP   40064          // 313 * 128, padded
#define EE   640000
#define FIN  33
#define HH   128
#define LL   8
#define ALPHA 0.1f
#define DEGCAP 64

// ---------------- scratch (no allocation allowed) ----------------
__device__ float  g_x0[NP * HH];
__device__ float  g_xca[NP * HH];           // fp32 ping
__device__ float  g_xcb[NP * HH];           // fp32 pong
__device__ __half g_xha[NP * HH];           // fp16 scaled xc mirror ping
__device__ __half g_xhb[NP * HH];           // fp16 scaled xc mirror pong
__device__ float  g_xx[NP * HH];            // aggregation output fp32
__device__ __half g_xxh[NP * HH];           // aggregation output fp16 (scaled)
__device__ __half g_wh[LL * HH * HH];       // W^T fp16: [l][n][k]
__device__ int    g_cnt[NN];
__device__ int    g_ecol[(size_t)NN * DEGCAP];
__device__ float  g_ew[(size_t)NN * DEGCAP];

// ---------------- launch 0: zero cnt + Wh = fp16(W^T) ----------------
__global__ void prep_kernel(const float* __restrict__ Wc) {
    int idx = blockIdx.x * blockDim.x + threadIdx.x;
    if (idx < NN) g_cnt[idx] = 0;
    if (idx < LL * HH * HH) {
        int l = idx >> 14;
        int rem = idx & 16383;
        int n = rem >> 7, k = rem & 127;
        g_wh[idx] = __float2half_rn(Wc[(l << 14) + k * HH + n]);
    }
}

// ---------------- launch 1: input projection + ELL scatter (fused) ----------------
#define SCAT_BLOCKS 2500
#define INP_BLOCKS  1250
__global__ void input_scatter_kernel(const float* __restrict__ x,
                                     const float* __restrict__ Win,
                                     const float* __restrict__ bin,
                                     const int* __restrict__ er,
                                     const int* __restrict__ ec,
                                     const float* __restrict__ ew) {
    if (blockIdx.x < SCAT_BLOCKS) {
        int e = blockIdx.x * 256 + threadIdx.x;
        if (e < EE) {
            int r = er[e];
            int s = atomicAdd(&g_cnt[r], 1);
            if (s < DEGCAP) {
                g_ecol[(size_t)r * DEGCAP + s] = ec[e];
                g_ew[(size_t)r * DEGCAP + s] = ew[e];
            }
        }
        return;
    }
    __shared__ float sW[HH * FIN];
    __shared__ float sx[FIN];
    int tid = threadIdx.x;
    for (int i = tid; i < HH * FIN; i += 256) sW[i] = Win[i];
    float b = (tid < HH) ? bin[tid] : 0.f;
    int row0 = (blockIdx.x - SCAT_BLOCKS) * 32;
    for (int r = 0; r < 32; r++) {
        int row = row0 + r;
        __syncthreads();
        if (tid < FIN) sx[tid] = x[row * FIN + tid];
        __syncthreads();
        if (tid < HH) {
            float s = b;
#pragma unroll
            for (int f = 0; f < FIN; f++) s += sW[tid * FIN + f] * sx[f];
            s = fmaxf(s, 0.0f);
            g_x0[row * HH + tid] = s;
            g_xca[row * HH + tid] = s;
            g_xha[row * HH + tid] = __float2half_rn(s);
        }
    }
}

// ---------------- SpMM: g_xx = invs*(A @ srcH) + 0.1*x0 ; g_xxh = g_xx * sxx ----
__device__ __forceinline__ void acc8(float* a, uint4 d, float w) {
    float2 f0 = __half22float2(*(__half2*)&d.x);
    float2 f1 = __half22float2(*(((__half2*)&d.x) + 1));
    float2 f2 = __half22float2(*(__half2*)&d.z);
    float2 f3 = __half22float2(*(((__half2*)&d.z) + 1));
    a[0] += w * f0.x; a[1] += w * f0.y;
    a[2] += w * f1.x; a[3] += w * f1.y;
    a[4] += w * f2.x; a[5] += w * f2.y;
    a[6] += w * f3.x; a[7] += w * f3.y;
}

__global__ void spmm_kernel(const __half* __restrict__ srcH, float invs, float sxx) {
    int gt = blockIdx.x * blockDim.x + threadIdx.x;
    int warp = gt >> 5;
    int lane = threadIdx.x & 31;
    int hsel = lane >> 4;
    int hl = lane & 15;
    int row = warp * 2 + hsel;
    if (row >= NN) return;
    int cn = g_cnt[row];
    cn = cn < DEGCAP ? cn : DEGCAP;
    const int* cb = g_ecol + (size_t)row * DEGCAP;
    const float* wb = g_ew + (size_t)row * DEGCAP;

    float aA[8] = {0.f, 0.f, 0.f, 0.f, 0.f, 0.f, 0.f, 0.f};
    float aB[8] = {0.f, 0.f, 0.f, 0.f, 0.f, 0.f, 0.f, 0.f};
    int fo = hl * 8;
    int i = 0;
    for (; i + 4 <= cn; i += 4) {
        int4 c = *(const int4*)&cb[i];
        float4 w = *(const float4*)&wb[i];
        uint4 d0 = *(const uint4*)&srcH[(size_t)c.x * HH + fo];
        uint4 d1 = *(const uint4*)&srcH[(size_t)c.y * HH + fo];
        uint4 d2 = *(const uint4*)&srcH[(size_t)c.z * HH + fo];
        uint4 d3 = *(const uint4*)&srcH[(size_t)c.w * HH + fo];
        acc8(aA, d0, w.x);
        acc8(aB, d1, w.y);
        acc8(aA, d2, w.z);
        acc8(aB, d3, w.w);
    }
    for (; i < cn; i++) {
        int c = cb[i];
        float w = wb[i];
        uint4 d = *(const uint4*)&srcH[(size_t)c * HH + fo];
        acc8(aA, d, w);
    }
#pragma unroll
    for (int j = 0; j < 8; j++) aA[j] += aB[j];

    const float* x0p = &g_x0[(size_t)row * HH + fo];
    float4 x00 = *(const float4*)x0p;
    float4 x01 = *(const float4*)(x0p + 4);
    float o[8];
    o[0] = invs * aA[0] + ALPHA * x00.x;
    o[1] = invs * aA[1] + ALPHA * x00.y;
    o[2] = invs * aA[2] + ALPHA * x00.z;
    o[3] = invs * aA[3] + ALPHA * x00.w;
    o[4] = invs * aA[4] + ALPHA * x01.x;
    o[5] = invs * aA[5] + ALPHA * x01.y;
    o[6] = invs * aA[6] + ALPHA * x01.z;
    o[7] = invs * aA[7] + ALPHA * x01.w;
    float* xxp = &g_xx[(size_t)row * HH + fo];
    *(float4*)xxp = make_float4(o[0], o[1], o[2], o[3]);
    *(float4*)(xxp + 4) = make_float4(o[4], o[5], o[6], o[7]);
    __half2 h0 = __floats2half2_rn(o[0] * sxx, o[1] * sxx);
    __half2 h1 = __floats2half2_rn(o[2] * sxx, o[3] * sxx);
    __half2 h2 = __floats2half2_rn(o[4] * sxx, o[5] * sxx);
    __half2 h3 = __floats2half2_rn(o[6] * sxx, o[7] * sxx);
    uint4 hp;
    hp.x = *(const unsigned*)&h0;
    hp.y = *(const unsigned*)&h1;
    hp.z = *(const unsigned*)&h2;
    hp.w = *(const unsigned*)&h3;
    *(uint4*)&g_xxh[(size_t)row * HH + fo] = hp;
}

// ---------------- GEMM (HMMA, BM=64, cp.async): out=(1-b)xx+b(xx@W); residual ----
// CTA 64x128x128, 8 warps (4m x 2n), warp tile 16x64. ldmatrix fragments.
#define MSTR 136
#define SMEM_MMA ((64 + 128) * MSTR * 2)

__device__ __forceinline__ void hmma(float* d, const uint32_t* a,
                                     uint32_t b0, uint32_t b1) {
    asm volatile(
        "mma.sync.aligned.m16n8k16.row.col.f32.f16.f16.f32 "
        "{%0,%1,%2,%3}, {%4,%5,%6,%7}, {%8,%9}, {%0,%1,%2,%3};"
        : "+f"(d[0]), "+f"(d[1]), "+f"(d[2]), "+f"(d[3])
        : "r"(a[0]), "r"(a[1]), "r"(a[2]), "r"(a[3]), "r"(b0), "r"(b1));
}
#define LDSM_X4(r, addr) \
    asm volatile("ldmatrix.sync.aligned.m8n8.x4.shared.b16 {%0,%1,%2,%3}, [%4];" \
        : "=r"((r)[0]), "=r"((r)[1]), "=r"((r)[2]), "=r"((r)[3]) : "r"(addr))
__device__ __forceinline__ void cpasync16(uint32_t saddr, const void* g) {
    asm volatile("cp.async.cg.shared.global [%0], [%1], 16;"
                 :: "r"(saddr), "l"(g) : "memory");
}

__global__ void __launch_bounds__(256) mma_gemm_kernel(const float* __restrict__ src,
                                                       float* __restrict__ dst,
                                                       __half* __restrict__ dstH,
                                                       const __half* __restrict__ Wh,
                                                       float omb, float bscale,
                                                       float hscale) {
    extern __shared__ __half sh[];
    __half* As = sh;               // [64][MSTR]
    __half* Bs = sh + 64 * MSTR;   // [128][MSTR], [n][k]

    int tid = threadIdx.x;
    int r0 = blockIdx.x * 64;
    const __half* Axh = g_xxh + (size_t)r0 * HH;

    uint32_t As_u = (uint32_t)__cvta_generic_to_shared(As);
    uint32_t Bs_u = (uint32_t)__cvta_generic_to_shared(Bs);

    // stage A (4 x 16B) and B (8 x 16B) per thread via cp.async
#pragma unroll
    for (int i = 0; i < 4; i++) {
        int idx = tid + i * 256;            // 0..1023
        int row = idx >> 4, q = idx & 15;
        cpasync16(As_u + (row * MSTR + q * 8) * 2, Axh + row * HH + q * 8);
    }
#pragma unroll
    for (int i = 0; i < 8; i++) {
        int idx = tid + i * 256;            // 0..2047
        int row = idx >> 4, q = idx & 15;
        cpasync16(Bs_u + (row * MSTR + q * 8) * 2, Wh + row * HH + q * 8);
    }
    asm volatile("cp.async.commit_group;" ::: "memory");
    asm volatile("cp.async.wait_group 0;" ::: "memory");
    __syncthreads();

    int wid = tid >> 5, lane = tid & 31;
    int wm = wid >> 1, wn = wid & 1;
    int qid = lane >> 2, qt = lane & 3;

    uint32_t aaddr = As_u + ((wm * 16 + (lane & 15)) * MSTR + (lane >> 4) * 8) * 2;
    uint32_t baddr[4];
#pragma unroll
    for (int j = 0; j < 4; j++)
        baddr[j] = Bs_u + ((wn * 64 + j * 16 + ((lane >> 4) & 1) * 8 + (lane & 7)) * MSTR
                           + ((lane >> 3) & 1) * 8) * 2;

    float acc[8][4];
#pragma unroll
    for (int nt = 0; nt < 8; nt++)
#pragma unroll
        for (int c = 0; c < 4; c++) acc[nt][c] = 0.f;

#pragma unroll
    for (int ks = 0; ks < 8; ks++) {
        uint32_t ko = ks * 32;              // 16 halfs = 32 bytes
        uint32_t a[4];
        LDSM_X4(a, aaddr + ko);
#pragma unroll
        for (int j = 0; j < 4; j++) {
            uint32_t bf[4];
            LDSM_X4(bf, baddr[j] + ko);
            hmma(acc[2 * j + 0], a, bf[0], bf[1]);
            hmma(acc[2 * j + 1], a, bf[2], bf[3]);
        }
    }

    // epilogue: dst = src + relu(omb*xx + bscale*acc); mirror = dst*hscale
#pragma unroll
    for (int h = 0; h < 2; h++) {
        int row = r0 + wm * 16 + qid + 8 * h;
        const float* xxr = &g_xx[(size_t)row * HH];
        const float* srr = &src[(size_t)row * HH];
        float* dsr = &dst[(size_t)row * HH];
        __half* dhr = &dstH[(size_t)row * HH];
#pragma unroll
        for (int nt = 0; nt < 8; nt++) {
            int col = wn * 64 + nt * 8 + qt * 2;
            float v0 = acc[nt][2 * h + 0];
            float v1 = acc[nt][2 * h + 1];
            float2 xx = *(const float2*)&xxr[col];
            float o0 = omb * xx.x + bscale * v0;
            float o1 = omb * xx.y + bscale * v1;
            float2 sv = *(const float2*)&srr[col];
            float d0 = sv.x + fmaxf(o0, 0.f);
            float d1 = sv.y + fmaxf(o1, 0.f);
            *(float2*)&dsr[col] = make_float2(d0, d1);
            __half2 hm = __floats2half2_rn(d0 * hscale, d1 * hscale);
            *(unsigned*)&dhr[col] = *(const unsigned*)&hm;
        }
    }
}

// ---------------- output projection: out = xc @ W_out^T + b_out ----------------
__global__ void out_proj_kernel(const float* __restrict__ xc,
                                const float* __restrict__ Wout,
                                const float* __restrict__ bout,
                                float* __restrict__ out) {
    int gt = blockIdx.x * blockDim.x + threadIdx.x;
    int row = gt >> 5;
    int lane = threadIdx.x & 31;
    if (row >= NN) return;
    float4 v = ((const float4*)xc)[row * 32 + lane];
#pragma unroll
    for (int c = 0; c < 3; c++) {
        float4 w = *(const float4*)&Wout[c * HH + lane * 4];
        float s = v.x * w.x + v.y * w.y + v.z * w.z + v.w * w.w;
#pragma unroll
        for (int o = 16; o; o >>= 1) s += __shfl_down_sync(0xFFFFFFFFu, s, o);
        if (lane == 0) out[row * 3 + c] = s + bout[c];
    }
}

extern "C" void kernel_launch(void* const* d_in, const int* in_sizes, int n_in,
                              void* d_out, int out_size) {
    const float* x    = (const float*)d_in[0];
    const int*   er   = (const int*)d_in[1];
    const int*   ec   = (const int*)d_in[2];
    const float* ew   = (const float*)d_in[3];
    const float* Win  = (const float*)d_in[4];
    const float* bin  = (const float*)d_in[5];
    const float* Wout = (const float*)d_in[6];
    const float* bout = (const float*)d_in[7];
    const float* Wc   = (const float*)d_in[8];
    float* out = (float*)d_out;

    float*  bufA; cudaGetSymbolAddress((void**)&bufA, g_xca);
    float*  bufB; cudaGetSymbolAddress((void**)&bufB, g_xcb);
    __half* hbufA; cudaGetSymbolAddress((void**)&hbufA, g_xha);
    __half* hbufB; cudaGetSymbolAddress((void**)&hbufB, g_xhb);
    __half* wh;   cudaGetSymbolAddress((void**)&wh, g_wh);

    cudaFuncSetAttribute(mma_gemm_kernel,
                         cudaFuncAttributeMaxDynamicSharedMemorySize, SMEM_MMA);

    prep_kernel<<<(LL * HH * HH + 255) / 256, 256>>>(Wc);                // launch 0
    input_scatter_kernel<<<SCAT_BLOCKS + INP_BLOCKS, 256>>>(x, Win, bin,
                                                            er, ec, ew); // launch 1

    for (int l = 0; l < LL; l++) {
        const float*  src  = (l & 1) ? bufB : bufA;
        float*        dst  = (l & 1) ? bufA : bufB;
        const __half* srcH = (l & 1) ? hbufB : hbufA;
        __half*       dstH = (l & 1) ? hbufA : hbufB;
        float beta = logf(0.5f / (float)(l + 1) + 1.0f);
        float invs = ldexpf(0.9f, 3 * l);            // 0.9 * 2^{3l}
        float sxx = ldexpf(1.0f, -3 * l);            // 2^{-3l}
        float bscale = beta * ldexpf(1.0f, 3 * l);   // beta * 2^{3l}
        float hscale = ldexpf(1.0f, -3 * (l + 1));   // 2^{-3(l+1)}
        spmm_kernel<<<(NN / 2 * 32 + 255) / 256, 256>>>(srcH, invs, sxx); // launch 2
        mma_gemm_kernel<<<NP / 64, 256, SMEM_MMA>>>(src, dst, dstH,       // launch 3
                                                    wh + (size_t)l * HH * HH,
                                                    1.0f - beta, bscale, hscale);
    }

    out_proj_kernel<<<(NN * 32 + 255) / 256, 256>>>(bufA, Wout, bout, out);
}

// round 17
// speedup vs baseline: 1.4274x; 1.3686x over previous
#include <cuda_runtime.h>
#include <cuda_fp16.h>
#include <math.h>
#include <stdint.h>

#define NN   40000
#define NP   40064          // 313 * 128, padded
#define EE   640000
#define FIN  33
#define HH   128
#define LL   8
#define ALPHA 0.1f
#define DEGCAP 64

// ---------------- scratch (no allocation allowed) ----------------
__device__ float  g_x0[NP * HH];
__device__ float  g_xca[NP * HH];           // fp32 ping
__device__ float  g_xcb[NP * HH];           // fp32 pong
__device__ __half g_xha[NP * HH];           // fp16 scaled xc mirror ping
__device__ __half g_xhb[NP * HH];           // fp16 scaled xc mirror pong
__device__ __half g_xxh[NP * HH];           // aggregation output fp16 (scaled; pad rows stay 0)
__device__ __half g_wh[LL * HH * HH];       // W'' fp16: [l][n][k] = (1-b)I + b W^T
__device__ int    g_cnt[NN];
__device__ int    g_ecol[(size_t)NN * DEGCAP];
__device__ float  g_ew[(size_t)NN * DEGCAP];

// ---------------- launch 0: zero cnt + W'' = (1-b)I + b*W^T in fp16 ----------------
__global__ void prep_kernel(const float* __restrict__ Wc) {
    int idx = blockIdx.x * blockDim.x + threadIdx.x;
    if (idx < NN) g_cnt[idx] = 0;
    if (idx < LL * HH * HH) {
        int l = idx >> 14;
        int rem = idx & 16383;
        int n = rem >> 7, k = rem & 127;
        float beta = logf(0.5f / (float)(l + 1) + 1.0f);
        float v = beta * Wc[(l << 14) + k * HH + n];
        if (n == k) v += 1.0f - beta;
        g_wh[idx] = __float2half_rn(v);
    }
}

// ---------------- launch 1: input projection + ELL scatter (fused) ----------------
#define SCAT_BLOCKS 2500
#define INP_BLOCKS  1250
__global__ void input_scatter_kernel(const float* __restrict__ x,
                                     const float* __restrict__ Win,
                                     const float* __restrict__ bin,
                                     const int* __restrict__ er,
                                     const int* __restrict__ ec,
                                     const float* __restrict__ ew) {
    if (blockIdx.x < SCAT_BLOCKS) {
        int e = blockIdx.x * 256 + threadIdx.x;
        if (e < EE) {
            int r = er[e];
            int s = atomicAdd(&g_cnt[r], 1);
            if (s < DEGCAP) {
                g_ecol[(size_t)r * DEGCAP + s] = ec[e];
                g_ew[(size_t)r * DEGCAP + s] = ew[e];
            }
        }
        return;
    }
    __shared__ float sW[HH * FIN];
    __shared__ float sx[FIN];
    int tid = threadIdx.x;
    for (int i = tid; i < HH * FIN; i += 256) sW[i] = Win[i];
    float b = (tid < HH) ? bin[tid] : 0.f;
    int row0 = (blockIdx.x - SCAT_BLOCKS) * 32;
    for (int r = 0; r < 32; r++) {
        int row = row0 + r;
        __syncthreads();
        if (tid < FIN) sx[tid] = x[row * FIN + tid];
        __syncthreads();
        if (tid < HH) {
            float s = b;
#pragma unroll
            for (int f = 0; f < FIN; f++) s += sW[tid * FIN + f] * sx[f];
            s = fmaxf(s, 0.0f);
            g_x0[row * HH + tid] = s;
            g_xca[row * HH + tid] = s;
            g_xha[row * HH + tid] = __float2half_rn(s);
        }
    }
}

// ---------------- SpMM: g_xxh = sxx * (invs*(A @ srcH) + 0.1*x0) ----------------
__device__ __forceinline__ void acc8(float* a, uint4 d, float w) {
    float2 f0 = __half22float2(*(__half2*)&d.x);
    float2 f1 = __half22float2(*(((__half2*)&d.x) + 1));
    float2 f2 = __half22float2(*(__half2*)&d.z);
    float2 f3 = __half22float2(*(((__half2*)&d.z) + 1));
    a[0] += w * f0.x; a[1] += w * f0.y;
    a[2] += w * f1.x; a[3] += w * f1.y;
    a[4] += w * f2.x; a[5] += w * f2.y;
    a[6] += w * f3.x; a[7] += w * f3.y;
}

__global__ void spmm_kernel(const __half* __restrict__ srcH, float invs, float sxx) {
    int gt = blockIdx.x * blockDim.x + threadIdx.x;
    int warp = gt >> 5;
    int lane = threadIdx.x & 31;
    int hsel = lane >> 4;
    int hl = lane & 15;
    int row = warp * 2 + hsel;
    if (row >= NN) return;
    int cn = g_cnt[row];
    cn = cn < DEGCAP ? cn : DEGCAP;
    const int* cb = g_ecol + (size_t)row * DEGCAP;
    const float* wb = g_ew + (size_t)row * DEGCAP;

    float aA[8] = {0.f, 0.f, 0.f, 0.f, 0.f, 0.f, 0.f, 0.f};
    float aB[8] = {0.f, 0.f, 0.f, 0.f, 0.f, 0.f, 0.f, 0.f};
    int fo = hl * 8;
    int i = 0;
    for (; i + 4 <= cn; i += 4) {
        int4 c = *(const int4*)&cb[i];
        float4 w = *(const float4*)&wb[i];
        uint4 d0 = *(const uint4*)&srcH[(size_t)c.x * HH + fo];
        uint4 d1 = *(const uint4*)&srcH[(size_t)c.y * HH + fo];
        uint4 d2 = *(const uint4*)&srcH[(size_t)c.z * HH + fo];
        uint4 d3 = *(const uint4*)&srcH[(size_t)c.w * HH + fo];
        acc8(aA, d0, w.x);
        acc8(aB, d1, w.y);
        acc8(aA, d2, w.z);
        acc8(aB, d3, w.w);
    }
    for (; i < cn; i++) {
        int c = cb[i];
        float w = wb[i];
        uint4 d = *(const uint4*)&srcH[(size_t)c * HH + fo];
        acc8(aA, d, w);
    }
#pragma unroll
    for (int j = 0; j < 8; j++) aA[j] += aB[j];

    const float* x0p = &g_x0[(size_t)row * HH + fo];
    float4 x00 = *(const float4*)x0p;
    float4 x01 = *(const float4*)(x0p + 4);
    float o[8];
    o[0] = invs * aA[0] + ALPHA * x00.x;
    o[1] = invs * aA[1] + ALPHA * x00.y;
    o[2] = invs * aA[2] + ALPHA * x00.z;
    o[3] = invs * aA[3] + ALPHA * x00.w;
    o[4] = invs * aA[4] + ALPHA * x01.x;
    o[5] = invs * aA[5] + ALPHA * x01.y;
    o[6] = invs * aA[6] + ALPHA * x01.z;
    o[7] = invs * aA[7] + ALPHA * x01.w;
    __half2 h0 = __floats2half2_rn(o[0] * sxx, o[1] * sxx);
    __half2 h1 = __floats2half2_rn(o[2] * sxx, o[3] * sxx);
    __half2 h2 = __floats2half2_rn(o[4] * sxx, o[5] * sxx);
    __half2 h3 = __floats2half2_rn(o[6] * sxx, o[7] * sxx);
    uint4 hp;
    hp.x = *(const unsigned*)&h0;
    hp.y = *(const unsigned*)&h1;
    hp.z = *(const unsigned*)&h2;
    hp.w = *(const unsigned*)&h3;
    *(uint4*)&g_xxh[(size_t)row * HH + fo] = hp;
}

// ---------------- GEMM (HMMA, BM=64, cp.async, smem epilogue) --------------------
// out = ascale * (xxh @ W''); dst = src + relu(out); dstH = dst * hscale.
// CTA 64x128x128, 8 warps (4m x 2n), warp tile 16x64. ldmatrix fragments.
#define MSTR 136
#define CSTR 132
#define SMEM_MMA ((64 + 128) * MSTR * 2)

__device__ __forceinline__ void hmma(float* d, const uint32_t* a,
                                     uint32_t b0, uint32_t b1) {
    asm volatile(
        "mma.sync.aligned.m16n8k16.row.col.f32.f16.f16.f32 "
        "{%0,%1,%2,%3}, {%4,%5,%6,%7}, {%8,%9}, {%0,%1,%2,%3};"
        : "+f"(d[0]), "+f"(d[1]), "+f"(d[2]), "+f"(d[3])
        : "r"(a[0]), "r"(a[1]), "r"(a[2]), "r"(a[3]), "r"(b0), "r"(b1));
}
#define LDSM_X4(r, addr) \
    asm volatile("ldmatrix.sync.aligned.m8n8.x4.shared.b16 {%0,%1,%2,%3}, [%4];" \
        : "=r"((r)[0]), "=r"((r)[1]), "=r"((r)[2]), "=r"((r)[3]) : "r"(addr))
__device__ __forceinline__ void cpasync16(uint32_t saddr, const void* g) {
    asm volatile("cp.async.cg.shared.global [%0], [%1], 16;"
                 :: "r"(saddr), "l"(g) : "memory");
}

__global__ void __launch_bounds__(256) mma_gemm_kernel(const float* __restrict__ src,
                                                       float* __restrict__ dst,
                                                       __half* __restrict__ dstH,
                                                       const __half* __restrict__ Wh,
                                                       float ascale, float hscale) {
    extern __shared__ char smraw[];
    __half* As = (__half*)smraw;          // [64][MSTR]
    __half* Bs = As + 64 * MSTR;          // [128][MSTR], [n][k]
    float*  Cs = (float*)smraw;           // [64][CSTR] (reuses tile space)

    int tid = threadIdx.x;
    int r0 = blockIdx.x * 64;
    const __half* Axh = g_xxh + (size_t)r0 * HH;

    uint32_t As_u = (uint32_t)__cvta_generic_to_shared(As);
    uint32_t Bs_u = (uint32_t)__cvta_generic_to_shared(Bs);

    // stage A (4 x 16B) and B (8 x 16B) per thread via cp.async
#pragma unroll
    for (int i = 0; i < 4; i++) {
        int idx = tid + i * 256;            // 0..1023
        int row = idx >> 4, q = idx & 15;
        cpasync16(As_u + (row * MSTR + q * 8) * 2, Axh + row * HH + q * 8);
    }
#pragma unroll
    for (int i = 0; i < 8; i++) {
        int idx = tid + i * 256;            // 0..2047
        int row = idx >> 4, q = idx & 15;
        cpasync16(Bs_u + (row * MSTR + q * 8) * 2, Wh + row * HH + q * 8);
    }
    asm volatile("cp.async.commit_group;" ::: "memory");
    asm volatile("cp.async.wait_group 0;" ::: "memory");
    __syncthreads();

    int wid = tid >> 5, lane = tid & 31;
    int wm = wid >> 1, wn = wid & 1;
    int qid = lane >> 2, qt = lane & 3;

    uint32_t aaddr = As_u + ((wm * 16 + (lane & 15)) * MSTR + (lane >> 4) * 8) * 2;
    uint32_t baddr[4];
#pragma unroll
    for (int j = 0; j < 4; j++)
        baddr[j] = Bs_u + ((wn * 64 + j * 16 + ((lane >> 4) & 1) * 8 + (lane & 7)) * MSTR
                           + ((lane >> 3) & 1) * 8) * 2;

    float acc[8][4];
#pragma unroll
    for (int nt = 0; nt < 8; nt++)
#pragma unroll
        for (int c = 0; c < 4; c++) acc[nt][c] = 0.f;

#pragma unroll
    for (int ks = 0; ks < 8; ks++) {
        uint32_t ko = ks * 32;              // 16 halfs = 32 bytes
        uint32_t a[4];
        LDSM_X4(a, aaddr + ko);
#pragma unroll
        for (int j = 0; j < 4; j++) {
            uint32_t bf[4];
            LDSM_X4(bf, baddr[j] + ko);
            hmma(acc[2 * j + 0], a, bf[0], bf[1]);
            hmma(acc[2 * j + 1], a, bf[2], bf[3]);
        }
    }

    // stage acc into smem (tiles are dead), then coalesced epilogue
    __syncthreads();
#pragma unroll
    for (int h = 0; h < 2; h++) {
        int rl = wm * 16 + qid + 8 * h;
#pragma unroll
        for (int nt = 0; nt < 8; nt++) {
            int col = wn * 64 + nt * 8 + qt * 2;
            *(float2*)&Cs[rl * CSTR + col] =
                make_float2(acc[nt][2 * h + 0], acc[nt][2 * h + 1]);
        }
    }
    __syncthreads();

#pragma unroll
    for (int i = 0; i < 8; i++) {
        int idx = tid + i * 256;            // 0..2047
        int rl = idx >> 5, c4 = (idx & 31) * 4;
        int row = r0 + rl;
        float4 cv = *(const float4*)&Cs[rl * CSTR + c4];
        float4 sv = *(const float4*)&src[(size_t)row * HH + c4];
        float4 dv;
        dv.x = sv.x + fmaxf(ascale * cv.x, 0.f);
        dv.y = sv.y + fmaxf(ascale * cv.y, 0.f);
        dv.z = sv.z + fmaxf(ascale * cv.z, 0.f);
        dv.w = sv.w + fmaxf(ascale * cv.w, 0.f);
        *(float4*)&dst[(size_t)row * HH + c4] = dv;
        __half2 h0 = __floats2half2_rn(dv.x * hscale, dv.y * hscale);
        __half2 h1 = __floats2half2_rn(dv.z * hscale, dv.w * hscale);
        uint2 hp;
        hp.x = *(const unsigned*)&h0;
        hp.y = *(const unsigned*)&h1;
        *(uint2*)&dstH[(size_t)row * HH + c4] = hp;
    }
}

// ---------------- output projection: out = xc @ W_out^T + b_out ----------------
__global__ void out_proj_kernel(const float* __restrict__ xc,
                                const float* __restrict__ Wout,
                                const float* __restrict__ bout,
                                float* __restrict__ out) {
    int gt = blockIdx.x * blockDim.x + threadIdx.x;
    int row = gt >> 5;
    int lane = threadIdx.x & 31;
    if (row >= NN) return;
    float4 v = ((const float4*)xc)[row * 32 + lane];
#pragma unroll
    for (int c = 0; c < 3; c++) {
        float4 w = *(const float4*)&Wout[c * HH + lane * 4];
        float s = v.x * w.x + v.y * w.y + v.z * w.z + v.w * w.w;
#pragma unroll
        for (int o = 16; o; o >>= 1) s += __shfl_down_sync(0xFFFFFFFFu, s, o);
        if (lane == 0) out[row * 3 + c] = s + bout[c];
    }
}

extern "C" void kernel_launch(void* const* d_in, const int* in_sizes, int n_in,
                              void* d_out, int out_size) {
    const float* x    = (const float*)d_in[0];
    const int*   er   = (const int*)d_in[1];
    const int*   ec   = (const int*)d_in[2];
    const float* ew   = (const float*)d_in[3];
    const float* Win  = (const float*)d_in[4];
    const float* bin  = (const float*)d_in[5];
    const float* Wout = (const float*)d_in[6];
    const float* bout = (const float*)d_in[7];
    const float* Wc   = (const float*)d_in[8];
    float* out = (float*)d_out;

    float*  bufA; cudaGetSymbolAddress((void**)&bufA, g_xca);
    float*  bufB; cudaGetSymbolAddress((void**)&bufB, g_xcb);
    __half* hbufA; cudaGetSymbolAddress((void**)&hbufA, g_xha);
    __half* hbufB; cudaGetSymbolAddress((void**)&hbufB, g_xhb);
    __half* wh;   cudaGetSymbolAddress((void**)&wh, g_wh);

    cudaFuncSetAttribute(mma_gemm_kernel,
                         cudaFuncAttributeMaxDynamicSharedMemorySize, SMEM_MMA);

    prep_kernel<<<(LL * HH * HH + 255) / 256, 256>>>(Wc);                // launch 0
    input_scatter_kernel<<<SCAT_BLOCKS + INP_BLOCKS, 256>>>(x, Win, bin,
                                                            er, ec, ew); // launch 1

    for (int l = 0; l < LL; l++) {
        const float*  src  = (l & 1) ? bufB : bufA;
        float*        dst  = (l & 1) ? bufA : bufB;
        const __half* srcH = (l & 1) ? hbufB : hbufA;
        __half*       dstH = (l & 1) ? hbufA : hbufB;
        float invs = ldexpf(0.9f, 3 * l);            // 0.9 * 2^{3l}
        float sxx = ldexpf(1.0f, -3 * l);            // 2^{-3l}
        float ascale = ldexpf(1.0f, 3 * l);          // 2^{3l}
        float hscale = ldexpf(1.0f, -3 * (l + 1));   // 2^{-3(l+1)}
        spmm_kernel<<<(NN / 2 * 32 + 255) / 256, 256>>>(srcH, invs, sxx); // launch 2
        mma_gemm_kernel<<<NP / 64, 256, SMEM_MMA>>>(src, dst, dstH,       // launch 3
                                                    wh + (size_t)l * HH * HH,
                                                    ascale, hscale);
    }

    out_proj_kernel<<<(NN * 32 + 255) / 256, 256>>>(bufA, Wout, bout, out);
}